// round 9
// baseline (speedup 1.0000x reference)
#include <cuda_runtime.h>
#include <cuda_fp16.h>
#include <cstdint>

#define MAXN 50000
#define MAXE 800000
#define HID  128
#define OUTC 64

typedef unsigned long long ull;

// ---------------------------------------------------------------------------
// Scratch (__device__ globals; no allocation allowed)
// ---------------------------------------------------------------------------
__device__ __half g_y1h[MAXN * HID];    // x @ W1, fp16
__device__ __half g_y2h[MAXN * OUTC];   // fused output, fp16
__device__ int    g_cnt [MAXN];          // zeroed at load; re-zeroed by lsm
__device__ int    g_off [MAXN + 1];
__device__ int    g_rank[MAXE];
__device__ int    g_csr [MAXE];
__device__ int    g_done;                // last-block ticket (self-resetting)

// ---------------------------------------------------------------------------
// Streams/events for fork-join inside graph capture
// ---------------------------------------------------------------------------
static cudaStream_t g_s1;
static cudaEvent_t  g_evA, g_evB;
static struct StreamInit {
    StreamInit() {
        cudaStreamCreateWithFlags(&g_s1, cudaStreamNonBlocking);
        cudaEventCreateWithFlags(&g_evA, cudaEventDisableTiming);
        cudaEventCreateWithFlags(&g_evB, cudaEventDisableTiming);
    }
} g_stream_init;

// ---------------------------------------------------------------------------
// Helpers
// ---------------------------------------------------------------------------
__device__ __forceinline__ uint32_t smem_u32(const void* p) {
    return (uint32_t)__cvta_generic_to_shared(p);
}
__device__ __forceinline__ ull pack2(float lo, float hi) {
    ull r;
    asm("mov.b64 %0, {%1, %2};" : "=l"(r) : "f"(lo), "f"(hi));
    return r;
}
__device__ __forceinline__ float2 unpack2(ull v) {
    float2 f;
    asm("mov.b64 {%0, %1}, %2;" : "=f"(f.x), "=f"(f.y) : "l"(v));
    return f;
}
__device__ __forceinline__ void fma2(ull& d, ull a, ull b) {
    asm("fma.rn.f32x2 %0, %1, %2, %3;" : "=l"(d) : "l"(a), "l"(b), "l"(d));
}
// Convert raw uint2 (4 halfs) -> float4
__device__ __forceinline__ float4 cvt_h4(uint2 u) {
    __half2 a = *reinterpret_cast<__half2*>(&u.x);
    __half2 b = *reinterpret_cast<__half2*>(&u.y);
    float2 fa = __half22float2(a), fb = __half22float2(b);
    return make_float4(fa.x, fa.y, fb.x, fb.y);
}

// ---------------------------------------------------------------------------
// count+rank+scan fused (last-block-done). 1024 threads/block.
// g_cnt pre-zeroed (by previous replay's lsm / initial load). g_done starts 0
// and is reset by the last block itself.
// ---------------------------------------------------------------------------
__global__ void __launch_bounds__(1024)
count_scan_kernel(const int* __restrict__ dst, int E2, int N) {
    int i = blockIdx.x * blockDim.x + threadIdx.x;
    if (i < E2) {
        int2 d = __ldg(reinterpret_cast<const int2*>(dst) + i);
        int2 r;
        r.x = atomicAdd(&g_cnt[d.x], 1);
        r.y = atomicAdd(&g_cnt[d.y], 1);
        reinterpret_cast<int2*>(g_rank)[i] = r;
    }
    __threadfence();
    __shared__ int isLast;
    if (threadIdx.x == 0) {
        int done = atomicAdd(&g_done, 1);
        isLast = (done == (int)gridDim.x - 1);
        if (isLast) g_done = 0;                 // reset for next replay
    }
    __syncthreads();
    if (!isLast) return;

    // ---- exclusive scan of g_cnt -> g_off (1024 threads, 4 elts/thread) ----
    __shared__ int warp_sums[32];
    __shared__ int carry_s;
    int t = threadIdx.x;
    int lane = t & 31, wid = t >> 5;
    int N4 = N >> 2;
    const int4* cnt4 = reinterpret_cast<const int4*>(g_cnt);
    int4* off4 = reinterpret_cast<int4*>(g_off);
    if (t == 0) carry_s = 0;
    __syncthreads();
    for (int base4 = 0; base4 < N4; base4 += 1024) {
        int idx4 = base4 + t;
        int4 v = (idx4 < N4) ? cnt4[idx4] : make_int4(0, 0, 0, 0);
        int s = v.x + v.y + v.z + v.w;
        int incl = s;
#pragma unroll
        for (int o = 1; o < 32; o <<= 1) {
            int u = __shfl_up_sync(~0u, incl, o);
            if (lane >= o) incl += u;
        }
        if (lane == 31) warp_sums[wid] = incl;
        __syncthreads();
        if (t < 32) {
            int w = warp_sums[t];
#pragma unroll
            for (int o = 1; o < 32; o <<= 1) {
                int u = __shfl_up_sync(~0u, w, o);
                if (t >= o) w += u;
            }
            warp_sums[t] = w;
        }
        __syncthreads();
        int woff = (wid > 0) ? warp_sums[wid - 1] : 0;
        int excl = incl - s + woff + carry_s;
        if (idx4 < N4) {
            int4 o;
            o.x = excl;
            o.y = excl + v.x;
            o.z = excl + v.x + v.y;
            o.w = excl + v.x + v.y + v.z;
            off4[idx4] = o;
        }
        __syncthreads();
        if (t == 0) carry_s += warp_sums[31];
        __syncthreads();
    }
    if (t == 0) g_off[N] = carry_s;
}

// Atomic-free scatter: position = off[dst] + rank.
__global__ void scatter_kernel(const int* __restrict__ src,
                               const int* __restrict__ dst, int E2) {
    int i = blockIdx.x * blockDim.x + threadIdx.x;
    if (i >= E2) return;
    int2 s = __ldg(reinterpret_cast<const int2*>(src) + i);
    int2 d = __ldg(reinterpret_cast<const int2*>(dst) + i);
    int2 r = reinterpret_cast<const int2*>(g_rank)[i];
    g_csr[__ldg(&g_off[d.x]) + r.x] = s.x;
    g_csr[__ldg(&g_off[d.y]) + r.y] = s.y;
}

// ---------------------------------------------------------------------------
// GEMM1 (tensor cores): y1h[N,128] = half( x[N,128] @ W1[128,128] )
// ---------------------------------------------------------------------------
#define G1_SMEM (2 * 128 * 136 * 2)   // As[128][136] + Ws[128][136], fp16

__global__ void __launch_bounds__(256, 2)
gemm1_kernel(const float* __restrict__ A, const float* __restrict__ W,
             __half* __restrict__ out, int N) {
    extern __shared__ char dynsm[];
    __half* As = reinterpret_cast<__half*>(dynsm);             // [128][136]
    __half* Ws = reinterpret_cast<__half*>(dynsm) + 128 * 136; // [128][136]

    const int t = threadIdx.x;
    const int row0 = blockIdx.x * 128;

#pragma unroll
    for (int i = 0; i < 16; i++) {
        int idx = t + i * 256;
        int m = idx >> 5;
        int c4 = idx & 31;
        int gr = row0 + m;
        float4 a = (gr < N)
            ? __ldg(reinterpret_cast<const float4*>(A + (size_t)gr * 128 + c4 * 4))
            : make_float4(0.f, 0.f, 0.f, 0.f);
        *reinterpret_cast<__half2*>(&As[m * 136 + c4 * 4])     = __floats2half2_rn(a.x, a.y);
        *reinterpret_cast<__half2*>(&As[m * 136 + c4 * 4 + 2]) = __floats2half2_rn(a.z, a.w);
    }
#pragma unroll
    for (int i = 0; i < 16; i++) {
        int idx = t + i * 256;
        int k = idx >> 5, c4 = idx & 31;
        float4 w = __ldg(reinterpret_cast<const float4*>(W + (size_t)k * 128 + c4 * 4));
        *reinterpret_cast<__half2*>(&Ws[k * 136 + c4 * 4])     = __floats2half2_rn(w.x, w.y);
        *reinterpret_cast<__half2*>(&Ws[k * 136 + c4 * 4 + 2]) = __floats2half2_rn(w.z, w.w);
    }
    __syncthreads();

    const int warp = t >> 5, lane = t & 31;
    const int m0 = warp * 16;

    float acc[16][4];
#pragma unroll
    for (int i = 0; i < 16; i++)
#pragma unroll
        for (int j = 0; j < 4; j++) acc[i][j] = 0.f;

#pragma unroll
    for (int kk = 0; kk < 8; kk++) {
        uint32_t a0, a1, a2, a3;
        uint32_t aaddr = smem_u32(
            &As[(m0 + (lane & 15)) * 136 + kk * 16 + ((lane >> 4) << 3)]);
        asm volatile("ldmatrix.sync.aligned.m8n8.x4.shared.b16 {%0,%1,%2,%3}, [%4];"
                     : "=r"(a0), "=r"(a1), "=r"(a2), "=r"(a3) : "r"(aaddr));
#pragma unroll
        for (int nt = 0; nt < 16; nt++) {
            uint32_t b0, b1;
            uint32_t baddr = smem_u32(&Ws[(kk * 16 + (lane & 15)) * 136 + nt * 8]);
            asm volatile("ldmatrix.sync.aligned.m8n8.x2.trans.shared.b16 {%0,%1}, [%2];"
                         : "=r"(b0), "=r"(b1) : "r"(baddr));
            asm volatile(
                "mma.sync.aligned.m16n8k16.row.col.f32.f16.f16.f32 "
                "{%0,%1,%2,%3}, {%4,%5,%6,%7}, {%8,%9}, {%0,%1,%2,%3};"
                : "+f"(acc[nt][0]), "+f"(acc[nt][1]),
                  "+f"(acc[nt][2]), "+f"(acc[nt][3])
                : "r"(a0), "r"(a1), "r"(a2), "r"(a3), "r"(b0), "r"(b1));
        }
    }

    const int g = lane >> 2, tg = lane & 3;
    const int r0 = row0 + m0 + g;
    const int r1 = r0 + 8;
#pragma unroll
    for (int nt = 0; nt < 16; nt++) {
        int col = nt * 8 + 2 * tg;
        if (r0 < N)
            *reinterpret_cast<__half2*>(&out[(size_t)r0 * 128 + col]) =
                __floats2half2_rn(acc[nt][0], acc[nt][1]);
        if (r1 < N)
            *reinterpret_cast<__half2*>(&out[(size_t)r1 * 128 + col]) =
                __floats2half2_rn(acc[nt][2], acc[nt][3]);
    }
}

// ---------------------------------------------------------------------------
// FUSED: pull-agg layer 1 into smem, then GEMM2. 512 threads, 16 warps,
// 4 nodes/warp. Raw uint2 held across the 8-wide load burst (low reg count);
// launch_bounds(512,2) -> 64 regs, no spills.
// ---------------------------------------------------------------------------
#define FUSE_SMEM ((64 * 132 + 128 * 64) * 4)

__global__ void __launch_bounds__(512, 2)
agg_gemm_kernel(const __half* __restrict__ Y1h, const float* __restrict__ W2,
                const float* __restrict__ b1, const float* __restrict__ b2,
                const float* __restrict__ cv1, __half* __restrict__ y2, int N) {
    extern __shared__ float sm[];
    float* As = sm;                  // [64][132]
    float* Ws = sm + 64 * 132;       // [128][64]

    const int t = threadIdx.x;
    const int row0 = blockIdx.x * 64;

#pragma unroll
    for (int i = 0; i < 4; i++) {
        int idx = t + i * 512;
        reinterpret_cast<float4*>(Ws)[idx] =
            __ldg(reinterpret_cast<const float4*>(W2) + idx);
    }

    // ---- Aggregation: warp w -> nodes row0+4w .. +4w+3; lane -> 4 cols ----
    {
        int warp = t >> 5, lane = t & 31;
        const uint2* Yv = reinterpret_cast<const uint2*>(Y1h);
        float sc = -fabsf(__ldg(cv1));
        float4 bb = __ldg(reinterpret_cast<const float4*>(b1) + lane);
#pragma unroll
        for (int ni = 0; ni < 4; ni++) {
            int m = warp * 4 + ni;
            int r = row0 + m;
            float4 o = make_float4(0.f, 0.f, 0.f, 0.f);
            if (r < N) {
                float4 acc = cvt_h4(__ldg(Yv + (size_t)r * 32 + lane)); // self
                int st = g_off[r], en = g_off[r + 1];
                int i = st;
                for (; i + 8 <= en; i += 8) {
                    uint2 u[8];
#pragma unroll
                    for (int j = 0; j < 8; j++) {
                        int s = __ldg(g_csr + i + j);
                        u[j] = __ldg(Yv + (size_t)s * 32 + lane);
                    }
#pragma unroll
                    for (int j = 0; j < 8; j++) {
                        float4 v = cvt_h4(u[j]);
                        acc.x += v.x; acc.y += v.y; acc.z += v.z; acc.w += v.w;
                    }
                }
                for (; i < en; i++) {
                    float4 v = cvt_h4(__ldg(Yv + (size_t)__ldg(g_csr + i) * 32 + lane));
                    acc.x += v.x; acc.y += v.y; acc.z += v.z; acc.w += v.w;
                }
                float deg = (float)(en - st + 1);
                o.x = fmaxf(0.f, sc * (acc.x + deg * bb.x));
                o.y = fmaxf(0.f, sc * (acc.y + deg * bb.y));
                o.z = fmaxf(0.f, sc * (acc.z + deg * bb.z));
                o.w = fmaxf(0.f, sc * (acc.w + deg * bb.w));
            }
            *reinterpret_cast<float4*>(&As[m * 132 + lane * 4]) = o;
        }
    }
    __syncthreads();

    // ---- GEMM phase: 64x64 tile, 512 threads, thread = 2 rows x 4 cols ----
    {
        int tx = t & 15;
        int ty = t >> 4;
        ull acc[2][2];
        acc[0][0] = acc[0][1] = acc[1][0] = acc[1][1] = 0ull;

#pragma unroll 8
        for (int k = 0; k < 128; k++) {
            ull w0 = *reinterpret_cast<const ull*>(&Ws[k * 64 + tx * 4]);
            ull w1 = *reinterpret_cast<const ull*>(&Ws[k * 64 + tx * 4 + 2]);
#pragma unroll
            for (int i = 0; i < 2; i++) {
                float a = As[(ty * 2 + i) * 132 + k];
                ull ad = pack2(a, a);
                fma2(acc[i][0], ad, w0);
                fma2(acc[i][1], ad, w1);
            }
        }

        float4 bb = __ldg(reinterpret_cast<const float4*>(b2) + tx);
#pragma unroll
        for (int i = 0; i < 2; i++) {
            int r = row0 + ty * 2 + i;
            if (r >= N) continue;
            float2 v0 = unpack2(acc[i][0]);
            float2 v1 = unpack2(acc[i][1]);
            __half2 h0 = __float22half2_rn(make_float2(v0.x + bb.x, v0.y + bb.y));
            __half2 h1 = __float22half2_rn(make_float2(v1.x + bb.z, v1.y + bb.w));
            uint2 pk;
            pk.x = *reinterpret_cast<unsigned*>(&h0);
            pk.y = *reinterpret_cast<unsigned*>(&h1);
            *reinterpret_cast<uint2*>(&y2[(size_t)r * OUTC + tx * 4]) = pk;
        }
    }
}

// ---------------------------------------------------------------------------
// Pull aggregation layer 2 (fp16 gather) + log_softmax.
// Re-zeros g_cnt for the next replay.
// ---------------------------------------------------------------------------
__global__ void __launch_bounds__(256)
pull_agg64_lsm_kernel(const __half* __restrict__ Yh,
                      const float* __restrict__ curv,
                      float* __restrict__ out, int N) {
    int gid = blockIdx.x * blockDim.x + threadIdx.x;
    if (gid < N) g_cnt[gid] = 0;   // prepare count buffer for next replay

    int warp = gid >> 5;
    int lane = threadIdx.x & 31;
    if (warp >= N) return;
    const __half2* Yv = reinterpret_cast<const __half2*>(Yh);
    float2 acc = __half22float2(__ldg(Yv + (size_t)warp * 32 + lane)); // self
    int st = g_off[warp], en = g_off[warp + 1];
    int i = st;
    for (; i + 8 <= en; i += 8) {
        __half2 u[8];
#pragma unroll
        for (int j = 0; j < 8; j++) {
            int s = __ldg(g_csr + i + j);
            u[j] = __ldg(Yv + (size_t)s * 32 + lane);
        }
#pragma unroll
        for (int j = 0; j < 8; j++) {
            float2 v = __half22float2(u[j]);
            acc.x += v.x; acc.y += v.y;
        }
    }
    for (; i < en; i++) {
        float2 v = __half22float2(__ldg(Yv + (size_t)__ldg(g_csr + i) * 32 + lane));
        acc.x += v.x; acc.y += v.y;
    }
    float sc = -fabsf(__ldg(curv));
    float a = sc * acc.x;
    float b = sc * acc.y;
    float m = fmaxf(a, b);
#pragma unroll
    for (int o = 16; o; o >>= 1) m = fmaxf(m, __shfl_xor_sync(~0u, m, o));
    float sum = expf(a - m) + expf(b - m);
#pragma unroll
    for (int o = 16; o; o >>= 1) sum += __shfl_xor_sync(~0u, sum, o);
    float lse = m + logf(sum);
    reinterpret_cast<float2*>(out)[(size_t)warp * 32 + lane] =
        make_float2(a - lse, b - lse);
}

// ---------------------------------------------------------------------------
// Launch. Submission order: count_scan #1, scatter #2, gemm1 #3,
// agg_gemm #4 (ncu capture slot), lsm #5.
// ---------------------------------------------------------------------------
extern "C" void kernel_launch(void* const* d_in, const int* in_sizes, int n_in,
                              void* d_out, int out_size) {
    const float* x   = (const float*)d_in[0];
    const int*   ei  = (const int*)d_in[1];
    const float* W1  = (const float*)d_in[2];
    const float* b1  = (const float*)d_in[3];
    const float* cv1 = (const float*)d_in[6];
    const float* W2  = (const float*)d_in[7];
    const float* b2  = (const float*)d_in[8];
    const float* cv2 = (const float*)d_in[11];
    float* out = (float*)d_out;

    int N = in_sizes[0] / HID;
    int E = in_sizes[1] / 2;
    if (N > MAXN) N = MAXN;
    if (E > MAXE) E = MAXE;
    const int* src = ei;
    const int* dst = ei + E;
    int E2 = E / 2;

    void *y1p, *y2p;
    cudaGetSymbolAddress(&y1p, g_y1h);
    cudaGetSymbolAddress(&y2p, g_y2h);

    cudaFuncSetAttribute(agg_gemm_kernel,
                         cudaFuncAttributeMaxDynamicSharedMemorySize, FUSE_SMEM);
    cudaFuncSetAttribute(gemm1_kernel,
                         cudaFuncAttributeMaxDynamicSharedMemorySize, G1_SMEM);

    // Fork: CSR build on side stream (overlaps gemm1)
    cudaEventRecord(g_evA, 0);
    cudaStreamWaitEvent(g_s1, g_evA, 0);
    count_scan_kernel<<<(E2 + 1023) / 1024, 1024, 0, g_s1>>>(dst, E2, N); // #1
    scatter_kernel<<<(E2 + 255) / 256, 256, 0, g_s1>>>(src, dst, E2);     // #2
    cudaEventRecord(g_evB, g_s1);

    // Main stream: y1 = half(x @ W1) on tensor cores
    gemm1_kernel<<<(N + 127) / 128, 256, G1_SMEM>>>(x, W1, (__half*)y1p, N); // #3

    // Join, then fused agg1+epi+gemm2  (ncu capture slot #4)
    cudaStreamWaitEvent(0, g_evB, 0);
    agg_gemm_kernel<<<(N + 63) / 64, 512, FUSE_SMEM>>>(
        (const __half*)y1p, W2, b1, b2, cv1, (__half*)y2p, N);            // #4

    // agg2 + log_softmax fused (+ g_cnt re-zero for next replay)
    pull_agg64_lsm_kernel<<<(N * 32 + 255) / 256, 256>>>(
        (const __half*)y2p, cv2, out, N);                                 // #5
}